// round 8
// baseline (speedup 1.0000x reference)
#include <cuda_runtime.h>

// infer/ref shape (2,7,7,3,256,256) -> N=98 images, C=3, H=W=256
#define NIMG   98
#define HH     256
#define WW     256
#define STRIP  8                             // rows per warp-task
#define NSTRIP (HH / STRIP)                  // 32
#define NTASK  (NIMG * NSTRIP)               // 3136
#define CH_STRIDE (HH * WW)                  // 65536 floats per channel
#define IMG_STRIDE (3 * CH_STRIDE)
#define CS4 (CH_STRIDE / 4)                  // 16384 float4 per channel
#define W4  (WW / 4)                         // 64 float4 per row

__device__ float g_partials[NTASK];
__device__ unsigned int g_count;             // zero-init; self-resets each run

// Load one row's D = sum_c(infer - ref) for this lane's 8 columns.
// Returns zeros for out-of-range rows (vertical zero padding / disabled prefetch).
static __device__ __forceinline__ void load_row(
    const float4* __restrict__ A, const float4* __restrict__ B,
    int gh, int lane, float4& x, float4& y)
{
    x = make_float4(0.f, 0.f, 0.f, 0.f);
    y = make_float4(0.f, 0.f, 0.f, 0.f);
    if ((unsigned)gh < (unsigned)HH) {
        const int off = gh * W4 + 2 * lane;
        // 12 independent LDG.128
        float4 a0 = A[off];            float4 b0 = B[off];
        float4 a1 = A[off + CS4];      float4 b1 = B[off + CS4];
        float4 a2 = A[off + 2*CS4];    float4 b2 = B[off + 2*CS4];
        float4 c0 = A[off + 1];        float4 e0 = B[off + 1];
        float4 c1 = A[off + 1 + CS4];  float4 e1 = B[off + 1 + CS4];
        float4 c2 = A[off + 1 + 2*CS4];float4 e2 = B[off + 1 + 2*CS4];
        x.x = (a0.x-b0.x)+(a1.x-b1.x)+(a2.x-b2.x);
        x.y = (a0.y-b0.y)+(a1.y-b1.y)+(a2.y-b2.y);
        x.z = (a0.z-b0.z)+(a1.z-b1.z)+(a2.z-b2.z);
        x.w = (a0.w-b0.w)+(a1.w-b1.w)+(a2.w-b2.w);
        y.x = (c0.x-e0.x)+(c1.x-e1.x)+(c2.x-e2.x);
        y.y = (c0.y-e0.y)+(c1.y-e1.y)+(c2.y-e2.y);
        y.z = (c0.z-e0.z)+(c1.z-e1.z)+(c2.z-e2.z);
        y.w = (c0.w-e0.w)+(c1.w-e1.w)+(c2.w-e2.w);
    }
}

__global__ void detail_loss_stream(const float* __restrict__ infer,
                                   const float* __restrict__ ref,
                                   float* __restrict__ out)
{
    const int lane = threadIdx.x;            // 0..31, lane owns cols 8*lane..8*lane+7
    const int task = blockIdx.x;             // one warp per block
    const int n    = task >> 5;              // image
    const int t    = task & 31;              // strip
    const int h0   = t * STRIP;

    const size_t base = (size_t)n * IMG_STRIDE;
    const float4* __restrict__ A = (const float4*)(infer + base);
    const float4* __restrict__ B = (const float4*)(ref   + base);

    // 2-deep software pipeline: while computing row i (needs p,c,n = rows
    // i-1,i,i+1), the loads for row i+2 (f) are already in flight.
    float4 px, py, cx, cy, nx, ny, fx, fy;
    load_row(A, B, h0 - 1, lane, px, py);    // row -1 (zeros at image top)
    load_row(A, B, h0,     lane, cx, cy);    // row 0
    load_row(A, B, h0 + 1, lane, nx, ny);    // row 1

    float acc = 0.f;
    #pragma unroll
    for (int i = 0; i < STRIP; i++) {
        // prefetch row i+2 (disabled on last iteration -> zeros, unused)
        const int gh = (i < STRIP - 1) ? (h0 + 2 + i) : -1;
        load_row(A, B, gh, lane, fx, fy);

        // horizontal term for row i: |d[w+1] - d[w-1]|, zero-padded in w
        float xm1 = __shfl_up_sync(0xffffffffu, cy.w, 1);
        if (lane == 0) xm1 = 0.f;
        float xp8 = __shfl_down_sync(0xffffffffu, cx.x, 1);
        if (lane == 31) xp8 = 0.f;
        acc += fabsf(cx.y - xm1)  + fabsf(cx.z - cx.x)
             + fabsf(cx.w - cx.y) + fabsf(cy.x - cx.z)
             + fabsf(cy.y - cx.w) + fabsf(cy.z - cy.x)
             + fabsf(cy.w - cy.y) + fabsf(xp8  - cy.z);

        // vertical term for row i: |d[r+1] - d[r-1]|
        acc += fabsf(nx.x - px.x) + fabsf(nx.y - px.y)
             + fabsf(nx.z - px.z) + fabsf(nx.w - px.w)
             + fabsf(ny.x - py.x) + fabsf(ny.y - py.y)
             + fabsf(ny.z - py.z) + fabsf(ny.w - py.w);

        px = cx; py = cy; cx = nx; cy = ny; nx = fx; ny = fy;
    }

    // warp reduction (fixed order -> deterministic)
    #pragma unroll
    for (int o = 16; o > 0; o >>= 1)
        acc += __shfl_xor_sync(0xffffffffu, acc, o);
    if (lane == 0) g_partials[task] = acc;

    // fused final reduction: last-finishing warp sums all partials
    int lastflag = 0;
    if (lane == 0) {
        __threadfence();
        unsigned old = atomicAdd(&g_count, 1u);
        lastflag = (old == NTASK - 1);
        if (lastflag) g_count = 0;           // reset for next graph replay
    }
    lastflag = __shfl_sync(0xffffffffu, lastflag, 0);
    if (lastflag) {
        __threadfence();                      // acquire all partials
        float s = 0.f;
        for (int i = lane; i < NTASK; i += 32) s += g_partials[i];
        #pragma unroll
        for (int o = 16; o > 0; o >>= 1)
            s += __shfl_xor_sync(0xffffffffu, s, o);
        if (lane == 0) {
            // result = A / (4 * 98 * 258 * 256): 0.5 grad coeff folded out,
            // /2 average of the two losses, mean denom 98*258*256 per term.
            out[0] = s * (1.0f / 25890816.0f);
        }
    }
}

extern "C" void kernel_launch(void* const* d_in, const int* in_sizes, int n_in,
                              void* d_out, int out_size)
{
    const float* infer = (const float*)d_in[0];
    const float* ref   = (const float*)d_in[1];
    float* out = (float*)d_out;
    (void)in_sizes; (void)n_in; (void)out_size;

    detail_loss_stream<<<NTASK, 32>>>(infer, ref, out);
}

// round 9
// speedup vs baseline: 1.0334x; 1.0334x over previous
#include <cuda_runtime.h>

// infer/ref shape (2,7,7,3,256,256) -> N=98 images, C=3, H=W=256
#define NIMG   98
#define HH     256
#define WW     256
#define STRIP  16                            // rows per warp-task
#define NSTRIP (HH / STRIP)                  // 16
#define NTASK  (NIMG * NSTRIP)               // 1568
#define CH_STRIDE (HH * WW)                  // 65536 floats per channel
#define IMG_STRIDE (3 * CH_STRIDE)
#define CS4 (CH_STRIDE / 4)                  // 16384 float4 per channel
#define W4  (WW / 4)                         // 64 float4 per row

__device__ float g_partials[NTASK];
__device__ unsigned int g_count;             // zero-init; self-resets each run

// Coalesced row load: lane owns float4 columns {lane, lane+32}.
// d0 = D[gh][4*lane .. 4*lane+3], d1 = D[gh][128+4*lane .. 128+4*lane+3],
// where D = sum_c (infer - ref). Zeros for out-of-image rows.
// Every LDG.128 here is warp-contiguous (512 B, 4 lines).
static __device__ __forceinline__ void load_row(
    const float4* __restrict__ A, const float4* __restrict__ B,
    int gh, int lane, float4& d0, float4& d1)
{
    d0 = make_float4(0.f, 0.f, 0.f, 0.f);
    d1 = make_float4(0.f, 0.f, 0.f, 0.f);
    if ((unsigned)gh < (unsigned)HH) {
        const int o0 = gh * W4 + lane;       // first half of the row
        const int o1 = o0 + 32;              // second half
        float4 a0 = A[o0];             float4 b0 = B[o0];
        float4 a1 = A[o0 + CS4];       float4 b1 = B[o0 + CS4];
        float4 a2 = A[o0 + 2*CS4];     float4 b2 = B[o0 + 2*CS4];
        float4 c0 = A[o1];             float4 e0 = B[o1];
        float4 c1 = A[o1 + CS4];       float4 e1 = B[o1 + CS4];
        float4 c2 = A[o1 + 2*CS4];     float4 e2 = B[o1 + 2*CS4];
        d0.x = (a0.x-b0.x)+(a1.x-b1.x)+(a2.x-b2.x);
        d0.y = (a0.y-b0.y)+(a1.y-b1.y)+(a2.y-b2.y);
        d0.z = (a0.z-b0.z)+(a1.z-b1.z)+(a2.z-b2.z);
        d0.w = (a0.w-b0.w)+(a1.w-b1.w)+(a2.w-b2.w);
        d1.x = (c0.x-e0.x)+(c1.x-e1.x)+(c2.x-e2.x);
        d1.y = (c0.y-e0.y)+(c1.y-e1.y)+(c2.y-e2.y);
        d1.z = (c0.z-e0.z)+(c1.z-e1.z)+(c2.z-e2.z);
        d1.w = (c0.w-e0.w)+(c1.w-e1.w)+(c2.w-e2.w);
    }
}

// Horizontal term |d[w+1] - d[w-1]| (zero-padded in w) for one row held as
// (d0, d1) across the warp.
static __device__ __forceinline__ float horiz_row(
    int lane, const float4& d0, const float4& d1)
{
    // d0 block: float4 index j = lane (cols 4j..4j+3)
    float l0 = __shfl_up_sync(0xffffffffu, d0.w, 1);       // element 4j-1
    if (lane == 0) l0 = 0.f;                               // col -1 pad
    float r0 = __shfl_down_sync(0xffffffffu, d0.x, 1);     // element 4j+4
    float seamR = __shfl_sync(0xffffffffu, d1.x, 0);       // col 128 (for lane 31)
    if (lane == 31) r0 = seamR;
    // d1 block: float4 index 32+lane
    float l1 = __shfl_up_sync(0xffffffffu, d1.w, 1);
    float seamL = __shfl_sync(0xffffffffu, d0.w, 31);      // col 127 (for lane 0)
    if (lane == 0) l1 = seamL;
    float r1 = __shfl_down_sync(0xffffffffu, d1.x, 1);
    if (lane == 31) r1 = 0.f;                              // col 256 pad

    return fabsf(d0.y - l0)   + fabsf(d0.z - d0.x)
         + fabsf(d0.w - d0.y) + fabsf(r0   - d0.z)
         + fabsf(d1.y - l1)   + fabsf(d1.z - d1.x)
         + fabsf(d1.w - d1.y) + fabsf(r1   - d1.z);
}

static __device__ __forceinline__ float vert_pair(
    const float4& n0, const float4& n1, const float4& p0, const float4& p1)
{
    return fabsf(n0.x - p0.x) + fabsf(n0.y - p0.y)
         + fabsf(n0.z - p0.z) + fabsf(n0.w - p0.w)
         + fabsf(n1.x - p1.x) + fabsf(n1.y - p1.y)
         + fabsf(n1.z - p1.z) + fabsf(n1.w - p1.w);
}

__global__ void detail_loss_stream(const float* __restrict__ infer,
                                   const float* __restrict__ ref,
                                   float* __restrict__ out)
{
    const int lane = threadIdx.x;            // 0..31
    const int task = blockIdx.x;             // one warp per block
    const int n    = task >> 4;              // image
    const int t    = task & 15;              // strip
    const int h0   = t * STRIP;

    const size_t base = (size_t)n * IMG_STRIDE;
    const float4* __restrict__ A = (const float4*)(infer + base);
    const float4* __restrict__ B = (const float4*)(ref   + base);

    // Rolling window over D rows: p = D[i-1], c = D[i].
    float4 p0, p1, c0, c1, n0, n1, f0, f1;
    load_row(A, B, h0 - 1, lane, p0, p1);    // halo above (zeros at image top)
    load_row(A, B, h0,     lane, c0, c1);

    float acc = 0.f;
    // Process 2 rows per iteration; the 24 LDG.128 for rows i+1 and i+2 are
    // issued back-to-back at the top of the body (high MLP), then consumed.
    #pragma unroll 1
    for (int k = 0; k < STRIP / 2; k++) {
        const int i = h0 + 2 * k;
        load_row(A, B, i + 1, lane, n0, n1);             // D[i+1]
        load_row(A, B, i + 2, lane, f0, f1);             // D[i+2] (halo on last k)

        // row i:   horizontal on c, vertical |D[i+1]-D[i-1]|
        acc += horiz_row(lane, c0, c1) + vert_pair(n0, n1, p0, p1);
        // row i+1: horizontal on n, vertical |D[i+2]-D[i]|
        acc += horiz_row(lane, n0, n1) + vert_pair(f0, f1, c0, c1);

        p0 = n0; p1 = n1; c0 = f0; c1 = f1;
    }

    // warp reduction (fixed order -> deterministic)
    #pragma unroll
    for (int o = 16; o > 0; o >>= 1)
        acc += __shfl_xor_sync(0xffffffffu, acc, o);
    if (lane == 0) g_partials[task] = acc;

    // fused final reduction: last-finishing warp sums all partials
    int lastflag = 0;
    if (lane == 0) {
        __threadfence();
        unsigned old = atomicAdd(&g_count, 1u);
        lastflag = (old == NTASK - 1);
        if (lastflag) g_count = 0;           // reset for next graph replay
    }
    lastflag = __shfl_sync(0xffffffffu, lastflag, 0);
    if (lastflag) {
        __threadfence();                      // acquire all partials
        float s = 0.f;
        for (int i = lane; i < NTASK; i += 32) s += g_partials[i];
        #pragma unroll
        for (int o = 16; o > 0; o >>= 1)
            s += __shfl_xor_sync(0xffffffffu, s, o);
        if (lane == 0) {
            // result = A / (4 * 98 * 258 * 256): 0.5 grad coeff folded out,
            // /2 average of the two losses, mean denom 98*258*256 per term.
            out[0] = s * (1.0f / 25890816.0f);
        }
    }
}

extern "C" void kernel_launch(void* const* d_in, const int* in_sizes, int n_in,
                              void* d_out, int out_size)
{
    const float* infer = (const float*)d_in[0];
    const float* ref   = (const float*)d_in[1];
    float* out = (float*)d_out;
    (void)in_sizes; (void)n_in; (void)out_size;

    detail_loss_stream<<<NTASK, 32>>>(infer, ref, out);
}